// round 7
// baseline (speedup 1.0000x reference)
#include <cuda_runtime.h>
#include <cuda_bf16.h>
#include <math.h>
#include <stdint.h>

// ---------------- problem constants ----------------
#define Bb 2
#define Tt 2048
#define Cc 1024
#define Hh 16
#define DH 64
#define BT (Bb*Tt)            // 4096
#define C3 (3*Cc)             // 3072
#define BH (Bb*Hh)            // 32

// output buffer layout (flatten-concat of the reference tuple, fp32)
#define N_OUT   ((size_t)Bb*Tt*Cc)                 // 4,194,304
#define OFF_DE  (N_OUT)
#define OFF_FE  (N_OUT + 1)
#define OFF_ATTN (N_OUT + 2)                       // only 8-byte aligned!
#define N_ATTN  ((size_t)Bb*Hh*Tt*Tt)
#define OFF_DISTS (OFF_ATTN + N_ATTN)

// ---------------- scratch ----------------
__device__ float g_qkv[(size_t)BT * C3];
__device__ float g_o[(size_t)BT * Cc];
__device__ __nv_bfloat16 g_ah[(size_t)BT * Cc];
__device__ __nv_bfloat16 g_al[(size_t)BT * Cc];
__device__ __nv_bfloat16 g_wh[(size_t)C3 * Cc];
__device__ __nv_bfloat16 g_wl[(size_t)C3 * Cc];
__device__ __nv_bfloat16 g_qh[(size_t)BH * Tt * DH];
__device__ __nv_bfloat16 g_ql[(size_t)BH * Tt * DH];
__device__ __nv_bfloat16 g_kh[(size_t)BH * Tt * DH];
__device__ __nv_bfloat16 g_kl[(size_t)BH * Tt * DH];

// ---------------- portable helpers (sm_80+) ----------------
__device__ __forceinline__ uint32_t smem_u32(const void* p) {
    uint32_t addr;
    asm("{ .reg .u64 tmp; cvta.to.shared.u64 tmp, %1; cvt.u32.u64 %0, tmp; }"
        : "=r"(addr) : "l"(p));
    return addr;
}
__device__ __forceinline__ void ldsm4(uint32_t r[4], uint32_t addr) {
    asm volatile("ldmatrix.sync.aligned.m8n8.x4.shared.b16 {%0,%1,%2,%3}, [%4];"
        : "=r"(r[0]), "=r"(r[1]), "=r"(r[2]), "=r"(r[3]) : "r"(addr));
}
__device__ __forceinline__ void mma_bf16(float c[4], const uint32_t a[4], const uint32_t b[2]) {
    asm volatile(
        "mma.sync.aligned.m16n8k16.row.col.f32.bf16.bf16.f32 "
        "{%0,%1,%2,%3}, {%4,%5,%6,%7}, {%8,%9}, {%0,%1,%2,%3};"
        : "+f"(c[0]), "+f"(c[1]), "+f"(c[2]), "+f"(c[3])
        : "r"(a[0]), "r"(a[1]), "r"(a[2]), "r"(a[3]), "r"(b[0]), "r"(b[1]));
}
__device__ __forceinline__ void cp_async16(uint32_t saddr, const void* gptr) {
    asm volatile("cp.async.cg.shared.global [%0], [%1], 16;" :: "r"(saddr), "l"(gptr));
}
#define CP_COMMIT() asm volatile("cp.async.commit_group;" ::: "memory")
#define CP_WAIT0()  asm volatile("cp.async.wait_group 0;" ::: "memory")

#define SPAD 40   // GEMM smem stride (bf16)
#define SK   72   // fused: stride for 64-wide tiles
#define SP   136  // fused: stride for 128-wide tiles

// ---------------- kernel: zero energy scalars + write dists ----------------
__global__ void dists_kernel(float* __restrict__ out) {
    size_t idx = (size_t)blockIdx.x * blockDim.x + threadIdx.x;
    if (idx < (size_t)Tt * Tt) {
        int i = (int)(idx / Tt);
        int j = (int)(idx % Tt);
        out[OFF_DISTS + idx] = fabsf((float)(i - j));
    }
    if (idx == 0) { out[OFF_DE] = 0.f; out[OFF_FE] = 0.f; }
}

// ---------------- kernel: fp32 -> bf16 hi/lo split ----------------
__global__ void cvt_split(const float* __restrict__ src,
                          __nv_bfloat16* __restrict__ hi,
                          __nv_bfloat16* __restrict__ lo, int n) {
    int idx = blockIdx.x * blockDim.x + threadIdx.x;
    if (idx >= n) return;
    float v = src[idx];
    __nv_bfloat16 h = __float2bfloat16(v);
    hi[idx] = h;
    lo[idx] = __float2bfloat16(v - __bfloat162float(h));
}

// ---------------- kernel: split q/k from g_qkv into head-major bf16 hi/lo ----------------
__global__ void cvt_qk(void) {
    int idx = blockIdx.x * blockDim.x + threadIdx.x;
    if (idx >= BT * Cc) return;
    int d = idx & 63;
    int h = (idx >> 6) & 15;
    int t = (idx >> 10) & 2047;
    int b = idx >> 21;
    size_t src = (size_t)(b * Tt + t) * C3 + h * DH + d;
    size_t dst = ((size_t)(b * Hh + h) * Tt + t) * DH + d;
    float q = g_qkv[src];
    float k = g_qkv[src + Cc];
    __nv_bfloat16 qh = __float2bfloat16(q);
    __nv_bfloat16 kh = __float2bfloat16(k);
    g_qh[dst] = qh; g_ql[dst] = __float2bfloat16(q - __bfloat162float(qh));
    g_kh[dst] = kh; g_kl[dst] = __float2bfloat16(k - __bfloat162float(kh));
}

// ---------------- warp-mma GEMM (cp.async double buffered, occ 2) ----------------
#define GT_TILE (128 * SPAD)
#define GT_SMEM (2 * 4 * GT_TILE * 2)        // 81920 bytes
__global__ __launch_bounds__(256, 2)
void mma_gemm_tn(const __nv_bfloat16* __restrict__ Ah, const __nv_bfloat16* __restrict__ Al,
                 const __nv_bfloat16* __restrict__ Wh, const __nv_bfloat16* __restrict__ Wl,
                 float* __restrict__ Cm, int K, int lda, int ldw, int ldc) {
    extern __shared__ __align__(16) __nv_bfloat16 dsmg[];
    int tid  = threadIdx.x;
    int warp = tid >> 5, lane = tid & 31;
    int m0 = blockIdx.y * 128;
    int n0 = blockIdx.x * 128;
    int wm = (warp & 3) * 32;
    int wn = (warp >> 2) * 64;

    const __nv_bfloat16* srcs[4] = { Ah + (size_t)m0 * lda, Al + (size_t)m0 * lda,
                                     Wh + (size_t)n0 * ldw, Wl + (size_t)n0 * ldw };
    int lds[4] = { lda, lda, ldw, ldw };
    uint32_t sb = smem_u32(dsmg);

    float c[16][4];
#pragma unroll
    for (int f = 0; f < 16; f++)
#pragma unroll
        for (int e = 0; e < 4; e++) c[f][e] = 0.f;

    int arow = lane & 15;
    int ablk = (lane >> 4) * 8;
    int nk = K / 32;

#pragma unroll
    for (int t = 0; t < 4; t++) {
        const __nv_bfloat16* s = srcs[t];
        int ld = lds[t];
#pragma unroll
        for (int it = 0; it < 2; it++) {
            int idx = tid + it * 256;
            int row = idx >> 2;
            int cc  = idx & 3;
            cp_async16(sb + (t * GT_TILE + row * SPAD + cc * 8) * 2,
                       s + (size_t)row * ld + cc * 8);
        }
    }
    CP_COMMIT();

    for (int kc = 0; kc < nk; kc++) {
        CP_WAIT0();
        __syncthreads();
        if (kc + 1 < nk) {
            int nb = (kc + 1) & 1;
            int k0 = (kc + 1) * 32;
#pragma unroll
            for (int t = 0; t < 4; t++) {
                const __nv_bfloat16* s = srcs[t] + k0;
                int ld = lds[t];
#pragma unroll
                for (int it = 0; it < 2; it++) {
                    int idx = tid + it * 256;
                    int row = idx >> 2;
                    int cc  = idx & 3;
                    cp_async16(sb + ((nb * 4 + t) * GT_TILE + row * SPAD + cc * 8) * 2,
                               s + (size_t)row * ld + cc * 8);
                }
            }
            CP_COMMIT();
        }
        uint32_t bo = (uint32_t)((kc & 1) * 4 * GT_TILE) * 2;

#pragma unroll
        for (int ks = 0; ks < 32; ks += 16) {
            uint32_t a_hi[2][4], a_lo[2][4];
#pragma unroll
            for (int mf = 0; mf < 2; mf++) {
                uint32_t off = ((wm + mf * 16 + arow) * SPAD + ks + ablk) * 2;
                ldsm4(a_hi[mf], sb + bo + 0 * GT_TILE * 2 + off);
                ldsm4(a_lo[mf], sb + bo + 1 * GT_TILE * 2 + off);
            }
            uint32_t b_hi[8][2], b_lo[8][2];
#pragma unroll
            for (int pr = 0; pr < 4; pr++) {
                uint32_t off = ((wn + pr * 16 + arow) * SPAD + ks + ablk) * 2;
                uint32_t t4[4];
                ldsm4(t4, sb + bo + 2 * GT_TILE * 2 + off);
                b_hi[pr*2+0][0] = t4[0]; b_hi[pr*2+0][1] = t4[2];
                b_hi[pr*2+1][0] = t4[1]; b_hi[pr*2+1][1] = t4[3];
                ldsm4(t4, sb + bo + 3 * GT_TILE * 2 + off);
                b_lo[pr*2+0][0] = t4[0]; b_lo[pr*2+0][1] = t4[2];
                b_lo[pr*2+1][0] = t4[1]; b_lo[pr*2+1][1] = t4[3];
            }
#pragma unroll
            for (int mf = 0; mf < 2; mf++)
#pragma unroll
                for (int nf = 0; nf < 8; nf++) {
                    mma_bf16(c[mf*8+nf], a_hi[mf], b_hi[nf]);
                    mma_bf16(c[mf*8+nf], a_hi[mf], b_lo[nf]);
                    mma_bf16(c[mf*8+nf], a_lo[mf], b_hi[nf]);
                }
        }
    }

    int r = lane >> 2, q2 = (lane & 3) * 2;
#pragma unroll
    for (int mf = 0; mf < 2; mf++)
#pragma unroll
        for (int nf = 0; nf < 8; nf++) {
            int m = m0 + wm + mf * 16 + r;
            int n = n0 + wn + nf * 8 + q2;
            float* f = c[mf*8+nf];
            *(float2*)&Cm[(size_t)m * ldc + n]       = make_float2(f[0], f[1]);
            *(float2*)&Cm[(size_t)(m + 8) * ldc + n] = make_float2(f[2], f[3]);
        }
}

// ---------------- fused attention helpers ----------------
// S tile (128x128) = Q K^T via split bf16, K-dim 64. No syncs inside.
__device__ __forceinline__ void compute_S(uint32_t sQh, uint32_t sQl,
                                          uint32_t sKh, uint32_t sKl,
                                          int wm, int wn, int lane, float (*c)[4]) {
#pragma unroll
    for (int f = 0; f < 16; f++)
#pragma unroll
        for (int e = 0; e < 4; e++) c[f][e] = 0.f;
    int arw = lane & 15, ablk = (lane >> 4) * 8;
#pragma unroll
    for (int ks = 0; ks < 64; ks += 16) {
        uint32_t a_hi[2][4], a_lo[2][4];
#pragma unroll
        for (int mf = 0; mf < 2; mf++) {
            uint32_t off = (uint32_t)((wm + mf * 16 + arw) * SK + ks + ablk) * 2;
            ldsm4(a_hi[mf], sQh + off);
            ldsm4(a_lo[mf], sQl + off);
        }
        uint32_t b_hi[8][2], b_lo[8][2];
#pragma unroll
        for (int pr = 0; pr < 4; pr++) {
            uint32_t off = (uint32_t)((wn + pr * 16 + arw) * SK + ks + ablk) * 2;
            uint32_t t4[4];
            ldsm4(t4, sKh + off);
            b_hi[pr*2+0][0] = t4[0]; b_hi[pr*2+0][1] = t4[2];
            b_hi[pr*2+1][0] = t4[1]; b_hi[pr*2+1][1] = t4[3];
            ldsm4(t4, sKl + off);
            b_lo[pr*2+0][0] = t4[0]; b_lo[pr*2+0][1] = t4[2];
            b_lo[pr*2+1][0] = t4[1]; b_lo[pr*2+1][1] = t4[3];
        }
#pragma unroll
        for (int mf = 0; mf < 2; mf++)
#pragma unroll
            for (int nf = 0; nf < 8; nf++) {
                mma_bf16(c[mf*8+nf], a_hi[mf], b_hi[nf]);
                mma_bf16(c[mf*8+nf], a_hi[mf], b_lo[nf]);
                mma_bf16(c[mf*8+nf], a_lo[mf], b_hi[nf]);
            }
    }
}

// load a 128x64 bf16 hi/lo tile pair into smem (stride SK)
__device__ __forceinline__ void load64(const __nv_bfloat16* __restrict__ gh,
                                       const __nv_bfloat16* __restrict__ gl,
                                       __nv_bfloat16* sh, __nv_bfloat16* sl, int tid) {
#pragma unroll
    for (int t = 0; t < 4; t++) {
        int idx = tid + t * 256;
        int row = idx >> 3, cc = idx & 7;
        *(uint4*)&sh[row * SK + cc * 8] = *(const uint4*)&gh[(size_t)row * DH + cc * 8];
        *(uint4*)&sl[row * SK + cc * 8] = *(const uint4*)&gl[(size_t)row * DH + cc * 8];
    }
}

// smem layout (bytes)
#define F_QH 0
#define F_QL 18432
#define F_KH 36864
#define F_KL 55296
#define F_VH 36864      // union with K (used after K consumed)
#define F_VL 54272
#define F_PH 73728
#define F_PL 108544
#define F_TSTAT 143360  // float[2][128]
#define F_TMAX  144384  // float[128]
#define F_RM    144896  // float[128]
#define F_RS    145408  // float[128] (running sum, then 1/sum)
#define F_ERED  145920  // float[16]
#define SMEM_FUSED 145984

// ---------------- fused attention: logits + softmax + attn write + energies + PV ----------------
__global__ __launch_bounds__(256)
void attn_fused(const float* __restrict__ dscales, float* __restrict__ d_out) {
    extern __shared__ __align__(16) char dsm[];
    __nv_bfloat16* sQh = (__nv_bfloat16*)(dsm + F_QH);
    __nv_bfloat16* sQl = (__nv_bfloat16*)(dsm + F_QL);
    __nv_bfloat16* sKh = (__nv_bfloat16*)(dsm + F_KH);
    __nv_bfloat16* sKl = (__nv_bfloat16*)(dsm + F_KL);
    __nv_bfloat16* sVh = (__nv_bfloat16*)(dsm + F_VH);
    __nv_bfloat16* sVl = (__nv_bfloat16*)(dsm + F_VL);
    __nv_bfloat16* sPh = (__nv_bfloat16*)(dsm + F_PH);
    __nv_bfloat16* sPl = (__nv_bfloat16*)(dsm + F_PL);
    float* tstat = (float*)(dsm + F_TSTAT);
    float* tmaxA = (float*)(dsm + F_TMAX);
    float* rmA   = (float*)(dsm + F_RM);
    float* rsA   = (float*)(dsm + F_RS);
    float* ered  = (float*)(dsm + F_ERED);

    int tid  = threadIdx.x;
    int warp = tid >> 5, lane = tid & 31;
    int wm = (warp & 3) * 32;
    int wn = (warp >> 2) * 64;
    int wn2 = (warp >> 2) * 32;
    int wnIdx = warp >> 2;
    int it = 15 - blockIdx.x;               // big tiles first
    int bh = blockIdx.y;
    int b = bh >> 4, h = bh & 15;
    int i0 = it * 128;
    float ds = dscales[h];

    uint32_t uQh = smem_u32(sQh), uQl = smem_u32(sQl);
    uint32_t uKh = smem_u32(sKh), uKl = smem_u32(sKl);
    uint32_t uVh = smem_u32(sVh), uVl = smem_u32(sVl);
    uint32_t uPh = smem_u32(sPh), uPl = smem_u32(sPl);

    size_t qoff = ((size_t)bh * Tt + i0) * DH;
    load64(g_qh + qoff, g_ql + qoff, sQh, sQl, tid);
    if (tid < 128) { rmA[tid] = -INFINITY; rsA[tid] = 0.f; }
    __syncthreads();

    int r = lane >> 2, q2 = (lane & 3) * 2;
    float c[16][4];

    // ============ pass 1: row max / sum ============
    for (int jt = 0; jt <= it; jt++) {
        int j0 = jt * 128;
        size_t koff = ((size_t)bh * Tt + j0) * DH;
        load64(g_kh + koff, g_kl + koff, sKh, sKl, tid);
        __syncthreads();
        compute_S(uQh, uQl, uKh, uKl, wm, wn, lane, c);
        // transform in place (+ causal mask)
#pragma unroll
        for (int mf = 0; mf < 2; mf++) {
            int ri0 = i0 + wm + mf * 16 + r;
#pragma unroll
            for (int nf = 0; nf < 8; nf++) {
                int j = j0 + wn + nf * 8 + q2;
                float* f = c[mf*8+nf];
                f[0] = (j     <= ri0    ) ? f[0]*0.125f - ds*(float)(ri0 - j)       : -INFINITY;
                f[1] = (j + 1 <= ri0    ) ? f[1]*0.125f - ds*(float)(ri0 - j - 1)   : -INFINITY;
                f[2] = (j     <= ri0 + 8) ? f[2]*0.125f - ds*(float)(ri0 + 8 - j)   : -INFINITY;
                f[3] = (j + 1 <= ri0 + 8) ? f[3]*0.125f - ds*(float)(ri0 + 8 - j-1) : -INFINITY;
            }
        }
        // tile row maxes
        float tmx[4] = {-INFINITY, -INFINITY, -INFINITY, -INFINITY};
#pragma unroll
        for (int mf = 0; mf < 2; mf++)
#pragma unroll
            for (int nf = 0; nf < 8; nf++) {
                float* f = c[mf*8+nf];
                tmx[mf*2+0] = fmaxf(tmx[mf*2+0], fmaxf(f[0], f[1]));
                tmx[mf*2+1] = fmaxf(tmx[mf*2+1], fmaxf(f[2], f[3]));
            }
#pragma unroll
        for (int off = 1; off <= 2; off <<= 1)
#pragma unroll
            for (int k = 0; k < 4; k++)
                tmx[k] = fmaxf(tmx[k], __shfl_xor_sync(0xFFFFFFFFu, tmx[k], off));
        if ((lane & 3) == 0) {
#pragma unroll
            for (int k = 0; k < 4; k++)
                tstat[wnIdx * 128 + wm + (k >> 1) * 16 + (k & 1) * 8 + r] = tmx[k];
        }
        __syncthreads();
        if (tid < 128) tmaxA[tid] = fmaxf(tstat[tid], tstat[128 + tid]);
        __syncthreads();
        // tile exp sums
        float tsm[4] = {0.f, 0.f, 0.f, 0.f};
#pragma unroll
        for (int mf = 0; mf < 2; mf++) {
            float m0 = tmaxA[wm + mf * 16 + r];
            float m1 = tmaxA[wm + mf * 16 + 8 + r];
#pragma unroll
            for (int nf = 0; nf < 8; nf++) {
                float* f = c[mf*8+nf];
                tsm[mf*2+0] += __expf(f[0] - m0) + __expf(f[1] - m0);
                tsm[mf*2+1] += __expf(f[2] - m1) + __expf(f[3] - m1);
            }
        }
#pragma unroll
        for (int off = 1; off <= 2; off <<= 1)
#pragma unroll
            for (int k = 0; k < 4; k++)
                tsm[k] += __shfl_xor_sync(0xFFFFFFFFu, tsm[k], off);
        if ((lane & 3) == 0) {
#pragma unroll
            for (int k = 0; k < 4; k++)
                tstat[wnIdx * 128 + wm + (k >> 1) * 16 + (k & 1) * 8 + r] = tsm[k];
        }
        __syncthreads();
        if (tid < 128) {
            float ts = tstat[tid] + tstat[128 + tid];
            float tm = tmaxA[tid];
            float mo = rmA[tid];
            float mn = fmaxf(mo, tm);
            rsA[tid] = rsA[tid] * __expf(mo - mn) + ts * __expf(tm - mn);
            rmA[tid] = mn;
        }
        __syncthreads();
    }
    if (tid < 128) rsA[tid] = 1.f / rsA[tid];
    __syncthreads();

    // ============ pass 2: attn write + energies + PV ============
    float c_o[8][4];
#pragma unroll
    for (int f = 0; f < 8; f++)
#pragma unroll
        for (int e = 0; e < 4; e++) c_o[f][e] = 0.f;
    float de = 0.f, fe = 0.f;
    size_t abase = OFF_ATTN + (size_t)bh * Tt * Tt;
    const float* Vb = g_qkv + (size_t)(b * Tt) * C3 + 2 * Cc + h * DH;

    for (int jt = 0; jt <= it; jt++) {
        int j0 = jt * 128;
        size_t koff = ((size_t)bh * Tt + j0) * DH;
        load64(g_kh + koff, g_kl + koff, sKh, sKl, tid);
        __syncthreads();
        compute_S(uQh, uQl, uKh, uKl, wm, wn, lane, c);

#pragma unroll
        for (int mf = 0; mf < 2; mf++) {
            int row0 = wm + mf * 16 + r;
            int ri0 = i0 + row0;
            float m0 = rmA[row0],     iv0 = rsA[row0];
            float m1 = rmA[row0 + 8], iv1 = rsA[row0 + 8];
#pragma unroll
            for (int nf = 0; nf < 8; nf++) {
                int jl = wn + nf * 8 + q2;
                int j = j0 + jl;
                float* f = c[mf*8+nf];
                float a0 = (j     <= ri0    ) ? __expf(f[0]*0.125f - ds*(float)(ri0-j)     - m0) * iv0 : 0.f;
                float a1 = (j + 1 <= ri0    ) ? __expf(f[1]*0.125f - ds*(float)(ri0-j-1)   - m0) * iv0 : 0.f;
                float a2 = (j     <= ri0 + 8) ? __expf(f[2]*0.125f - ds*(float)(ri0+8-j)   - m1) * iv1 : 0.f;
                float a3 = (j + 1 <= ri0 + 8) ? __expf(f[3]*0.125f - ds*(float)(ri0+8-j-1) - m1) * iv1 : 0.f;
                *(float2*)&d_out[abase + (size_t)ri0 * Tt + j]       = make_float2(a0, a1);
                *(float2*)&d_out[abase + (size_t)(ri0 + 8) * Tt + j] = make_float2(a2, a3);
                de += a0*(float)(ri0-j) + a1*(float)(ri0-j-1) + a2*(float)(ri0+8-j) + a3*(float)(ri0+8-j-1);
                fe -= a0*__logf(a0+1e-9f) + a1*__logf(a1+1e-9f) + a2*__logf(a2+1e-9f) + a3*__logf(a3+1e-9f);
                __nv_bfloat16 h0 = __float2bfloat16(a0), h1 = __float2bfloat16(a1);
                __nv_bfloat16 h2 = __float2bfloat16(a2), h3 = __float2bfloat16(a3);
                __nv_bfloat162 hv01; hv01.x = h0; hv01.y = h1;
                __nv_bfloat162 hv23; hv23.x = h2; hv23.y = h3;
                *(__nv_bfloat162*)&sPh[row0 * SP + jl]       = hv01;
                *(__nv_bfloat162*)&sPh[(row0 + 8) * SP + jl] = hv23;
                __nv_bfloat162 lv01, lv23;
                lv01.x = __float2bfloat16(a0 - __bfloat162float(h0));
                lv01.y = __float2bfloat16(a1 - __bfloat162float(h1));
                lv23.x = __float2bfloat16(a2 - __bfloat162float(h2));
                lv23.y = __float2bfloat16(a3 - __bfloat162float(h3));
                *(__nv_bfloat162*)&sPl[row0 * SP + jl]       = lv01;
                *(__nv_bfloat162*)&sPl[(row0 + 8) * SP + jl] = lv23;
            }
        }
        __syncthreads();     // all ldsm on sK done; P complete

        // V^T tile (64 x 128), bf16 hi/lo, overlays sK region
#pragma unroll
        for (int t = 0; t < 32; t++) {
            int idx = tid + t * 256;
            int kk = idx >> 6, d = idx & 63;
            float xv = Vb[(size_t)(j0 + kk) * C3 + d];
            __nv_bfloat16 hh = __float2bfloat16(xv);
            sVh[d * SP + kk] = hh;
            sVl[d * SP + kk] = __float2bfloat16(xv - __bfloat162float(hh));
        }
        __syncthreads();

        // PV: O += P (128x128) @ V^T(64x128)^T, warp tile 32x32
        {
            int arw = lane & 15, ablk2 = (lane >> 4) * 8;
#pragma unroll
            for (int ks = 0; ks < 128; ks += 16) {
                uint32_t a_hi[2][4], a_lo[2][4];
#pragma unroll
                for (int mf = 0; mf < 2; mf++) {
                    uint32_t off = (uint32_t)((wm + mf * 16 + arw) * SP + ks + ablk2) * 2;
                    ldsm4(a_hi[mf], uPh + off);
                    ldsm4(a_lo[mf], uPl + off);
                }
                uint32_t b_hi[4][2], b_lo[4][2];
#pragma unroll
                for (int pr = 0; pr < 2; pr++) {
                    uint32_t off = (uint32_t)((wn2 + pr * 16 + arw) * SP + ks + ablk2) * 2;
                    uint32_t t4[4];
                    ldsm4(t4, uVh + off);
                    b_hi[pr*2+0][0] = t4[0]; b_hi[pr*2+0][1] = t4[2];
                    b_hi[pr*2+1][0] = t4[1]; b_hi[pr*2+1][1] = t4[3];
                    ldsm4(t4, uVl + off);
                    b_lo[pr*2+0][0] = t4[0]; b_lo[pr*2+0][1] = t4[2];
                    b_lo[pr*2+1][0] = t4[1]; b_lo[pr*2+1][1] = t4[3];
                }
#pragma unroll
                for (int mf = 0; mf < 2; mf++)
#pragma unroll
                    for (int nf = 0; nf < 4; nf++) {
                        mma_bf16(c_o[mf*4+nf], a_hi[mf], b_hi[nf]);
                        mma_bf16(c_o[mf*4+nf], a_hi[mf], b_lo[nf]);
                        mma_bf16(c_o[mf*4+nf], a_lo[mf], b_hi[nf]);
                    }
            }
        }
        __syncthreads();     // before next jt overwrites sK/sV
    }

    // O epilogue -> g_o
#pragma unroll
    for (int mf = 0; mf < 2; mf++)
#pragma unroll
        for (int nf = 0; nf < 4; nf++) {
            int m = i0 + wm + mf * 16 + r;
            int n = wn2 + nf * 8 + q2;
            float* f = c_o[mf*4+nf];
            *(float2*)&g_o[(size_t)(b * Tt + m) * Cc + h * DH + n]     = make_float2(f[0], f[1]);
            *(float2*)&g_o[(size_t)(b * Tt + m + 8) * Cc + h * DH + n] = make_float2(f[2], f[3]);
        }

    // zero-fill upper attn region (cols beyond (it+1)*128)
    int w2 = (15 - it) * 64;     // float2s per row
    for (int row = 0; row < 128; row++) {
        size_t base = abase + (size_t)(i0 + row) * Tt + (it + 1) * 128;
        for (int c2 = tid; c2 < w2; c2 += 256)
            *(float2*)&d_out[base + c2 * 2] = make_float2(0.f, 0.f);
    }

    // energies
#pragma unroll
    for (int off = 16; off > 0; off >>= 1) {
        de += __shfl_xor_sync(0xFFFFFFFFu, de, off);
        fe += __shfl_xor_sync(0xFFFFFFFFu, fe, off);
    }
    if (lane == 0) { ered[warp] = de; ered[8 + warp] = fe; }
    __syncthreads();
    if (tid == 0) {
        float sde = 0.f, sfe = 0.f;
#pragma unroll
        for (int w = 0; w < 8; w++) { sde += ered[w]; sfe += ered[8 + w]; }
        atomicAdd(&d_out[OFF_DE], sde * (1.f / 65536.f));
        atomicAdd(&d_out[OFF_FE], sfe * (1.f / 65536.f));
    }
}

// ---------------- launch ----------------
extern "C" void kernel_launch(void* const* d_in, const int* in_sizes, int n_in,
                              void* d_out, int out_size) {
    const float* x       = (const float*)d_in[0];
    const float* qkv_w   = (const float*)d_in[1];
    const float* proj_w  = (const float*)d_in[2];
    const float* dscales = (const float*)d_in[3];
    float* out = (float*)d_out;

    float *p_qkv, *p_o;
    __nv_bfloat16 *p_ah, *p_al, *p_wh, *p_wl;
    cudaGetSymbolAddress((void**)&p_qkv, g_qkv);
    cudaGetSymbolAddress((void**)&p_o,   g_o);
    cudaGetSymbolAddress((void**)&p_ah,  g_ah);
    cudaGetSymbolAddress((void**)&p_al,  g_al);
    cudaGetSymbolAddress((void**)&p_wh,  g_wh);
    cudaGetSymbolAddress((void**)&p_wl,  g_wl);

    cudaFuncSetAttribute(mma_gemm_tn, cudaFuncAttributeMaxDynamicSharedMemorySize, GT_SMEM);
    cudaFuncSetAttribute(attn_fused,  cudaFuncAttributeMaxDynamicSharedMemorySize, SMEM_FUSED);

    // 1. dists + zero scalars
    dists_kernel<<<(unsigned)(((size_t)Tt * Tt + 255) / 256), 256>>>(out);

    // 2. split x and qkv_w
    cvt_split<<<(BT * Cc + 255) / 256, 256>>>(x, p_ah, p_al, BT * Cc);
    cvt_split<<<(C3 * Cc + 255) / 256, 256>>>(qkv_w, p_wh, p_wl, C3 * Cc);

    // 3. QKV GEMM
    {
        dim3 grid(C3 / 128, BT / 128);
        mma_gemm_tn<<<grid, 256, GT_SMEM>>>(p_ah, p_al, p_wh, p_wl, p_qkv, Cc, Cc, Cc, C3);
    }

    // 4. q/k head-major split
    cvt_qk<<<(BT * Cc + 255) / 256, 256>>>();

    // 5. fused attention
    {
        dim3 grid(Tt / 128, BH);
        attn_fused<<<grid, 256, SMEM_FUSED>>>(dscales, out);
    }

    // 6. split o and proj_w, then proj GEMM -> out[0..N_OUT)
    cvt_split<<<(BT * Cc + 255) / 256, 256>>>(p_o, p_ah, p_al, BT * Cc);
    cvt_split<<<(Cc * Cc + 255) / 256, 256>>>(proj_w, p_wh, p_wl, Cc * Cc);
    {
        dim3 grid(Cc / 128, BT / 128);
        mma_gemm_tn<<<grid, 256, GT_SMEM>>>(p_ah, p_al, p_wh, p_wl, out, Cc, Cc, Cc, Cc);
    }
}

// round 8
// speedup vs baseline: 1.1148x; 1.1148x over previous
#include <cuda_runtime.h>
#include <cuda_bf16.h>
#include <math.h>
#include <stdint.h>

// ---------------- problem constants ----------------
#define Bb 2
#define Tt 2048
#define Cc 1024
#define Hh 16
#define DH 64
#define BT (Bb*Tt)            // 4096
#define C3 (3*Cc)             // 3072
#define BH (Bb*Hh)            // 32

// output buffer layout (flatten-concat of the reference tuple, fp32)
#define N_OUT   ((size_t)Bb*Tt*Cc)                 // 4,194,304
#define OFF_DE  (N_OUT)
#define OFF_FE  (N_OUT + 1)
#define OFF_ATTN (N_OUT + 2)                       // only 8-byte aligned!
#define N_ATTN  ((size_t)Bb*Hh*Tt*Tt)
#define OFF_DISTS (OFF_ATTN + N_ATTN)

// ---------------- scratch ----------------
__device__ float g_qkv[(size_t)BT * C3];
__device__ float g_o[(size_t)BT * Cc];
__device__ __nv_bfloat16 g_ah[(size_t)BT * Cc];
__device__ __nv_bfloat16 g_al[(size_t)BT * Cc];
__device__ __nv_bfloat16 g_wh[(size_t)C3 * Cc];
__device__ __nv_bfloat16 g_wl[(size_t)C3 * Cc];
__device__ __nv_bfloat16 g_qh[(size_t)BH * Tt * DH];
__device__ __nv_bfloat16 g_ql[(size_t)BH * Tt * DH];
__device__ __nv_bfloat16 g_kh[(size_t)BH * Tt * DH];
__device__ __nv_bfloat16 g_kl[(size_t)BH * Tt * DH];

// ---------------- portable helpers (sm_80+) ----------------
__device__ __forceinline__ uint32_t smem_u32(const void* p) {
    uint32_t addr;
    asm("{ .reg .u64 tmp; cvta.to.shared.u64 tmp, %1; cvt.u32.u64 %0, tmp; }"
        : "=r"(addr) : "l"(p));
    return addr;
}
__device__ __forceinline__ void ldsm4(uint32_t r[4], uint32_t addr) {
    asm volatile("ldmatrix.sync.aligned.m8n8.x4.shared.b16 {%0,%1,%2,%3}, [%4];"
        : "=r"(r[0]), "=r"(r[1]), "=r"(r[2]), "=r"(r[3]) : "r"(addr));
}
__device__ __forceinline__ void mma_bf16(float c[4], const uint32_t a[4], const uint32_t b[2]) {
    asm volatile(
        "mma.sync.aligned.m16n8k16.row.col.f32.bf16.bf16.f32 "
        "{%0,%1,%2,%3}, {%4,%5,%6,%7}, {%8,%9}, {%0,%1,%2,%3};"
        : "+f"(c[0]), "+f"(c[1]), "+f"(c[2]), "+f"(c[3])
        : "r"(a[0]), "r"(a[1]), "r"(a[2]), "r"(a[3]), "r"(b[0]), "r"(b[1]));
}
__device__ __forceinline__ void cp_async16(uint32_t saddr, const void* gptr) {
    asm volatile("cp.async.cg.shared.global [%0], [%1], 16;" :: "r"(saddr), "l"(gptr));
}
#define CP_COMMIT() asm volatile("cp.async.commit_group;" ::: "memory")
#define CP_WAIT0()  asm volatile("cp.async.wait_group 0;" ::: "memory")

#define SPAD 40   // smem row stride in bf16 (80B; ldmatrix conflict-free)

// ---------------- kernel: zero energy scalars + write dists ----------------
__global__ void dists_kernel(float* __restrict__ out) {
    size_t idx = (size_t)blockIdx.x * blockDim.x + threadIdx.x;
    if (idx < (size_t)Tt * Tt) {
        int i = (int)(idx / Tt);
        int j = (int)(idx % Tt);
        out[OFF_DISTS + idx] = fabsf((float)(i - j));
    }
    if (idx == 0) { out[OFF_DE] = 0.f; out[OFF_FE] = 0.f; }
}

// ---------------- kernel: fp32 -> bf16 hi/lo split ----------------
__global__ void cvt_split(const float* __restrict__ src,
                          __nv_bfloat16* __restrict__ hi,
                          __nv_bfloat16* __restrict__ lo, int n) {
    int idx = blockIdx.x * blockDim.x + threadIdx.x;
    if (idx >= n) return;
    float v = src[idx];
    __nv_bfloat16 h = __float2bfloat16(v);
    hi[idx] = h;
    lo[idx] = __float2bfloat16(v - __bfloat162float(h));
}

// ---------------- kernel: split q/k from g_qkv into head-major bf16 hi/lo ----------------
__global__ void cvt_qk(void) {
    int idx = blockIdx.x * blockDim.x + threadIdx.x;
    if (idx >= BT * Cc) return;
    int d = idx & 63;
    int h = (idx >> 6) & 15;
    int t = (idx >> 10) & 2047;
    int b = idx >> 21;
    size_t src = (size_t)(b * Tt + t) * C3 + h * DH + d;
    size_t dst = ((size_t)(b * Hh + h) * Tt + t) * DH + d;
    float q = g_qkv[src];
    float k = g_qkv[src + Cc];
    __nv_bfloat16 qh = __float2bfloat16(q);
    __nv_bfloat16 kh = __float2bfloat16(k);
    g_qh[dst] = qh; g_ql[dst] = __float2bfloat16(q - __bfloat162float(qh));
    g_kh[dst] = kh; g_kl[dst] = __float2bfloat16(k - __bfloat162float(kh));
}

// ---------------- warp-mma GEMM (cp.async double buffered, occ 2) ----------------
#define GT_TILE (128 * SPAD)
#define GT_SMEM (2 * 4 * GT_TILE * 2)        // 81920 bytes
__global__ __launch_bounds__(256, 2)
void mma_gemm_tn(const __nv_bfloat16* __restrict__ Ah, const __nv_bfloat16* __restrict__ Al,
                 const __nv_bfloat16* __restrict__ Wh, const __nv_bfloat16* __restrict__ Wl,
                 float* __restrict__ Cm, int K, int lda, int ldw, int ldc) {
    extern __shared__ __align__(16) __nv_bfloat16 dsmg[];
    int tid  = threadIdx.x;
    int warp = tid >> 5, lane = tid & 31;
    int m0 = blockIdx.y * 128;
    int n0 = blockIdx.x * 128;
    int wm = (warp & 3) * 32;
    int wn = (warp >> 2) * 64;

    const __nv_bfloat16* srcs[4] = { Ah + (size_t)m0 * lda, Al + (size_t)m0 * lda,
                                     Wh + (size_t)n0 * ldw, Wl + (size_t)n0 * ldw };
    int lds[4] = { lda, lda, ldw, ldw };
    uint32_t sb = smem_u32(dsmg);

    float c[16][4];
#pragma unroll
    for (int f = 0; f < 16; f++)
#pragma unroll
        for (int e = 0; e < 4; e++) c[f][e] = 0.f;

    int arow = lane & 15;
    int ablk = (lane >> 4) * 8;
    int nk = K / 32;

#pragma unroll
    for (int t = 0; t < 4; t++) {
        const __nv_bfloat16* s = srcs[t];
        int ld = lds[t];
#pragma unroll
        for (int it = 0; it < 2; it++) {
            int idx = tid + it * 256;
            int row = idx >> 2;
            int cc  = idx & 3;
            cp_async16(sb + (t * GT_TILE + row * SPAD + cc * 8) * 2,
                       s + (size_t)row * ld + cc * 8);
        }
    }
    CP_COMMIT();

    for (int kc = 0; kc < nk; kc++) {
        CP_WAIT0();
        __syncthreads();
        if (kc + 1 < nk) {
            int nb = (kc + 1) & 1;
            int k0 = (kc + 1) * 32;
#pragma unroll
            for (int t = 0; t < 4; t++) {
                const __nv_bfloat16* s = srcs[t] + k0;
                int ld = lds[t];
#pragma unroll
                for (int it = 0; it < 2; it++) {
                    int idx = tid + it * 256;
                    int row = idx >> 2;
                    int cc  = idx & 3;
                    cp_async16(sb + ((nb * 4 + t) * GT_TILE + row * SPAD + cc * 8) * 2,
                               s + (size_t)row * ld + cc * 8);
                }
            }
            CP_COMMIT();
        }
        uint32_t bo = (uint32_t)((kc & 1) * 4 * GT_TILE) * 2;

#pragma unroll
        for (int ks = 0; ks < 32; ks += 16) {
            uint32_t a_hi[2][4], a_lo[2][4];
#pragma unroll
            for (int mf = 0; mf < 2; mf++) {
                uint32_t off = ((wm + mf * 16 + arow) * SPAD + ks + ablk) * 2;
                ldsm4(a_hi[mf], sb + bo + 0 * GT_TILE * 2 + off);
                ldsm4(a_lo[mf], sb + bo + 1 * GT_TILE * 2 + off);
            }
            uint32_t b_hi[8][2], b_lo[8][2];
#pragma unroll
            for (int pr = 0; pr < 4; pr++) {
                uint32_t off = ((wn + pr * 16 + arow) * SPAD + ks + ablk) * 2;
                uint32_t t4[4];
                ldsm4(t4, sb + bo + 2 * GT_TILE * 2 + off);
                b_hi[pr*2+0][0] = t4[0]; b_hi[pr*2+0][1] = t4[2];
                b_hi[pr*2+1][0] = t4[1]; b_hi[pr*2+1][1] = t4[3];
                ldsm4(t4, sb + bo + 3 * GT_TILE * 2 + off);
                b_lo[pr*2+0][0] = t4[0]; b_lo[pr*2+0][1] = t4[2];
                b_lo[pr*2+1][0] = t4[1]; b_lo[pr*2+1][1] = t4[3];
            }
#pragma unroll
            for (int mf = 0; mf < 2; mf++)
#pragma unroll
                for (int nf = 0; nf < 8; nf++) {
                    mma_bf16(c[mf*8+nf], a_hi[mf], b_hi[nf]);
                    mma_bf16(c[mf*8+nf], a_hi[mf], b_lo[nf]);
                    mma_bf16(c[mf*8+nf], a_lo[mf], b_hi[nf]);
                }
        }
    }

    int r = lane >> 2, q2 = (lane & 3) * 2;
#pragma unroll
    for (int mf = 0; mf < 2; mf++)
#pragma unroll
        for (int nf = 0; nf < 8; nf++) {
            int m = m0 + wm + mf * 16 + r;
            int n = n0 + wn + nf * 8 + q2;
            float* f = c[mf*8+nf];
            *(float2*)&Cm[(size_t)m * ldc + n]       = make_float2(f[0], f[1]);
            *(float2*)&Cm[(size_t)(m + 8) * ldc + n] = make_float2(f[2], f[3]);
        }
}

// ---------------- warp-mma logits (occ 2) ----------------
__global__ __launch_bounds__(256, 2)
void mma_logits(const float* __restrict__ dscales, float* __restrict__ out) {
    if (blockIdx.x > blockIdx.y) return;
    __shared__ __align__(16) __nv_bfloat16 sm[4][128 * SPAD];
    int tid  = threadIdx.x;
    int warp = tid >> 5, lane = tid & 31;
    int bh = blockIdx.z;
    int h = bh & 15;
    int i0 = blockIdx.y * 128;
    int j0 = blockIdx.x * 128;
    int wm = (warp & 3) * 32;
    int wn = (warp >> 2) * 64;

    size_t qbase = ((size_t)bh * Tt + i0) * DH;
    size_t kbase = ((size_t)bh * Tt + j0) * DH;
    const __nv_bfloat16* srcs[4] = { g_qh + qbase, g_ql + qbase, g_kh + kbase, g_kl + kbase };

    uint32_t sbase[4];
#pragma unroll
    for (int t = 0; t < 4; t++) sbase[t] = smem_u32(sm[t]);

    float c[16][4];
#pragma unroll
    for (int f = 0; f < 16; f++)
#pragma unroll
        for (int e = 0; e < 4; e++) c[f][e] = 0.f;

    int arow = lane & 15;
    int ablk = (lane >> 4) * 8;

#pragma unroll
    for (int k0 = 0; k0 < DH; k0 += 32) {
#pragma unroll
        for (int t = 0; t < 4; t++) {
            const __nv_bfloat16* s = srcs[t] + k0;
#pragma unroll
            for (int it = 0; it < 2; it++) {
                int idx = tid + it * 256;
                int row = idx >> 2;
                int cc  = idx & 3;
                uint4 v = *(const uint4*)(s + (size_t)row * DH + cc * 8);
                *(uint4*)(&sm[t][row * SPAD + cc * 8]) = v;
            }
        }
        __syncthreads();

#pragma unroll
        for (int ks = 0; ks < 32; ks += 16) {
            uint32_t a_hi[2][4], a_lo[2][4];
#pragma unroll
            for (int mf = 0; mf < 2; mf++) {
                uint32_t off = ((wm + mf * 16 + arow) * SPAD + ks + ablk) * 2;
                ldsm4(a_hi[mf], sbase[0] + off);
                ldsm4(a_lo[mf], sbase[1] + off);
            }
            uint32_t b_hi[8][2], b_lo[8][2];
#pragma unroll
            for (int pr = 0; pr < 4; pr++) {
                uint32_t off = ((wn + pr * 16 + arow) * SPAD + ks + ablk) * 2;
                uint32_t t4[4];
                ldsm4(t4, sbase[2] + off);
                b_hi[pr*2+0][0] = t4[0]; b_hi[pr*2+0][1] = t4[2];
                b_hi[pr*2+1][0] = t4[1]; b_hi[pr*2+1][1] = t4[3];
                ldsm4(t4, sbase[3] + off);
                b_lo[pr*2+0][0] = t4[0]; b_lo[pr*2+0][1] = t4[2];
                b_lo[pr*2+1][0] = t4[1]; b_lo[pr*2+1][1] = t4[3];
            }
#pragma unroll
            for (int mf = 0; mf < 2; mf++)
#pragma unroll
                for (int nf = 0; nf < 8; nf++) {
                    mma_bf16(c[mf*8+nf], a_hi[mf], b_hi[nf]);
                    mma_bf16(c[mf*8+nf], a_hi[mf], b_lo[nf]);
                    mma_bf16(c[mf*8+nf], a_lo[mf], b_hi[nf]);
                }
        }
        __syncthreads();
    }

    float ds = dscales[h];
    int r = lane >> 2, q2 = (lane & 3) * 2;
    size_t abase = OFF_ATTN + (size_t)bh * Tt * Tt;
#pragma unroll
    for (int mf = 0; mf < 2; mf++)
#pragma unroll
        for (int nf = 0; nf < 8; nf++) {
            int i = i0 + wm + mf * 16 + r;
            int j = j0 + wn + nf * 8 + q2;
            float* f = c[mf*8+nf];
            float2 v0, v1;
            v0.x = f[0] * 0.125f - ds * (float)(i - j);
            v0.y = f[1] * 0.125f - ds * (float)(i - j - 1);
            v1.x = f[2] * 0.125f - ds * (float)(i + 8 - j);
            v1.y = f[3] * 0.125f - ds * (float)(i + 8 - j - 1);
            *(float2*)&out[abase + (size_t)i * Tt + j]       = v0;
            *(float2*)&out[abase + (size_t)(i + 8) * Tt + j] = v1;
        }
}

// ---------------- softmax + energies: register-resident ----------------
__global__ __launch_bounds__(256) void softmax_kernel(float* __restrict__ d_out) {
    __shared__ float red[4][8];
    int i   = blockIdx.x;
    int bh  = blockIdx.y;
    int tid = threadIdx.x;
    int lane = tid & 31, wid = tid >> 5;
    size_t arow = OFF_ATTN + ((size_t)bh * Tt + i) * Tt;

    float v[8];
    float lmax = -INFINITY;
#pragma unroll
    for (int k = 0; k < 4; k++) {
        int j = 2 * (tid + 256 * k);
        float a = -INFINITY, b = -INFINITY;
        if (j <= i) {
            float2 s = *(const float2*)&d_out[arow + j];
            a = s.x;
            if (j + 1 <= i) b = s.y;
        }
        v[2*k] = a; v[2*k+1] = b;
        lmax = fmaxf(lmax, fmaxf(a, b));
    }
#pragma unroll
    for (int off = 16; off > 0; off >>= 1)
        lmax = fmaxf(lmax, __shfl_xor_sync(0xFFFFFFFFu, lmax, off));
    if (lane == 0) red[0][wid] = lmax;
    __syncthreads();
    float m = red[0][0];
#pragma unroll
    for (int w = 1; w < 8; w++) m = fmaxf(m, red[0][w]);

    float lsum = 0.f;
#pragma unroll
    for (int k = 0; k < 8; k++) {
        v[k] = __expf(v[k] - m);
        lsum += v[k];
    }
#pragma unroll
    for (int off = 16; off > 0; off >>= 1)
        lsum += __shfl_xor_sync(0xFFFFFFFFu, lsum, off);
    if (lane == 0) red[1][wid] = lsum;
    __syncthreads();
    float tot = 0.f;
#pragma unroll
    for (int w = 0; w < 8; w++) tot += red[1][w];
    float inv = 1.f / tot;

    float de = 0.f, fe = 0.f;
#pragma unroll
    for (int k = 0; k < 4; k++) {
        int j = 2 * (tid + 256 * k);
        float a0 = v[2*k] * inv;
        float a1 = v[2*k+1] * inv;
        *(float2*)&d_out[arow + j] = make_float2(a0, a1);
        de += a0 * (float)(i - j) + a1 * (float)(i - j - 1);
        fe -= a0 * __logf(a0 + 1e-9f) + a1 * __logf(a1 + 1e-9f);
    }
#pragma unroll
    for (int off = 16; off > 0; off >>= 1) {
        de += __shfl_xor_sync(0xFFFFFFFFu, de, off);
        fe += __shfl_xor_sync(0xFFFFFFFFu, fe, off);
    }
    if (lane == 0) { red[2][wid] = de; red[3][wid] = fe; }
    __syncthreads();
    if (tid == 0) {
        float sde = 0.f, sfe = 0.f;
#pragma unroll
        for (int w = 0; w < 8; w++) { sde += red[2][w]; sfe += red[3][w]; }
        atomicAdd(&d_out[OFF_DE], sde * (1.f / 65536.f));
        atomicAdd(&d_out[OFF_FE], sfe * (1.f / 65536.f));
    }
}

// ---------------- PV via warp-mma (occ 2): O = A @ V (in-kernel bf16 split) ----------------
__global__ __launch_bounds__(256, 2) void pv_mma(const float* __restrict__ d_out_c,
                                                 float* __restrict__ o) {
    __shared__ __align__(16) __nv_bfloat16 sAh[128 * SPAD];
    __shared__ __align__(16) __nv_bfloat16 sAl[128 * SPAD];
    __shared__ __align__(16) __nv_bfloat16 sVh[64 * SPAD];
    __shared__ __align__(16) __nv_bfloat16 sVl[64 * SPAD];
    int it = blockIdx.x;
    int bh = blockIdx.y;
    int b = bh >> 4, h = bh & 15;
    int i0 = it * 128;
    int tid  = threadIdx.x;
    int warp = tid >> 5, lane = tid & 31;
    int wm = (warp & 3) * 32;
    int wn = (warp >> 2) * 32;

    const float* Arow = d_out_c + OFF_ATTN + (size_t)bh * Tt * Tt;
    const float* Vb = g_qkv + (size_t)(b * Tt) * C3 + 2 * Cc + h * DH;

    uint32_t sbAh = smem_u32(sAh), sbAl = smem_u32(sAl);
    uint32_t sbVh = smem_u32(sVh), sbVl = smem_u32(sVl);

    float c[8][4];
#pragma unroll
    for (int f = 0; f < 8; f++)
#pragma unroll
        for (int e = 0; e < 4; e++) c[f][e] = 0.f;

    int arw = lane & 15;
    int ablk = (lane >> 4) * 8;
    int kmax = i0 + 128;

    for (int k0 = 0; k0 < kmax; k0 += 32) {
#pragma unroll
        for (int t = 0; t < 8; t++) {
            int idx = tid + t * 256;
            int row = idx >> 4;
            int cc  = idx & 15;
            float2 s = *(const float2*)&Arow[(size_t)(i0 + row) * Tt + k0 + cc * 2];
            __nv_bfloat16 h0 = __float2bfloat16(s.x);
            __nv_bfloat16 h1 = __float2bfloat16(s.y);
            sAh[row * SPAD + cc*2]     = h0;
            sAh[row * SPAD + cc*2 + 1] = h1;
            sAl[row * SPAD + cc*2]     = __float2bfloat16(s.x - __bfloat162float(h0));
            sAl[row * SPAD + cc*2 + 1] = __float2bfloat16(s.y - __bfloat162float(h1));
        }
#pragma unroll
        for (int t = 0; t < 8; t++) {
            int idx = tid + t * 256;
            int kk = idx >> 6;
            int d  = idx & 63;
            float xv = Vb[(size_t)(k0 + kk) * C3 + d];
            __nv_bfloat16 hh = __float2bfloat16(xv);
            sVh[d * SPAD + kk] = hh;
            sVl[d * SPAD + kk] = __float2bfloat16(xv - __bfloat162float(hh));
        }
        __syncthreads();

#pragma unroll
        for (int ks = 0; ks < 32; ks += 16) {
            uint32_t a_hi[2][4], a_lo[2][4];
#pragma unroll
            for (int mf = 0; mf < 2; mf++) {
                uint32_t off = ((wm + mf * 16 + arw) * SPAD + ks + ablk) * 2;
                ldsm4(a_hi[mf], sbAh + off);
                ldsm4(a_lo[mf], sbAl + off);
            }
            uint32_t b_hi[4][2], b_lo[4][2];
#pragma unroll
            for (int pr = 0; pr < 2; pr++) {
                uint32_t off = ((wn + pr * 16 + arw) * SPAD + ks + ablk) * 2;
                uint32_t t4[4];
                ldsm4(t4, sbVh + off);
                b_hi[pr*2+0][0] = t4[0]; b_hi[pr*2+0][1] = t4[2];
                b_hi[pr*2+1][0] = t4[1]; b_hi[pr*2+1][1] = t4[3];
                ldsm4(t4, sbVl + off);
                b_lo[pr*2+0][0] = t4[0]; b_lo[pr*2+0][1] = t4[2];
                b_lo[pr*2+1][0] = t4[1]; b_lo[pr*2+1][1] = t4[3];
            }
#pragma unroll
            for (int mf = 0; mf < 2; mf++)
#pragma unroll
                for (int nf = 0; nf < 4; nf++) {
                    mma_bf16(c[mf*4+nf], a_hi[mf], b_hi[nf]);
                    mma_bf16(c[mf*4+nf], a_hi[mf], b_lo[nf]);
                    mma_bf16(c[mf*4+nf], a_lo[mf], b_hi[nf]);
                }
        }
        __syncthreads();
    }

    int r = lane >> 2, q2 = (lane & 3) * 2;
#pragma unroll
    for (int mf = 0; mf < 2; mf++)
#pragma unroll
        for (int nf = 0; nf < 4; nf++) {
            int m = i0 + wm + mf * 16 + r;
            int n = wn + nf * 8 + q2;
            float* f = c[mf*4+nf];
            *(float2*)&o[(size_t)(b * Tt + m) * Cc + h * DH + n]       = make_float2(f[0], f[1]);
            *(float2*)&o[(size_t)(b * Tt + m + 8) * Cc + h * DH + n]   = make_float2(f[2], f[3]);
        }
}

// ---------------- launch ----------------
extern "C" void kernel_launch(void* const* d_in, const int* in_sizes, int n_in,
                              void* d_out, int out_size) {
    const float* x       = (const float*)d_in[0];
    const float* qkv_w   = (const float*)d_in[1];
    const float* proj_w  = (const float*)d_in[2];
    const float* dscales = (const float*)d_in[3];
    float* out = (float*)d_out;

    float *p_qkv, *p_o;
    __nv_bfloat16 *p_ah, *p_al, *p_wh, *p_wl;
    cudaGetSymbolAddress((void**)&p_qkv, g_qkv);
    cudaGetSymbolAddress((void**)&p_o,   g_o);
    cudaGetSymbolAddress((void**)&p_ah,  g_ah);
    cudaGetSymbolAddress((void**)&p_al,  g_al);
    cudaGetSymbolAddress((void**)&p_wh,  g_wh);
    cudaGetSymbolAddress((void**)&p_wl,  g_wl);

    cudaFuncSetAttribute(mma_gemm_tn, cudaFuncAttributeMaxDynamicSharedMemorySize, GT_SMEM);

    // 1. dists + zero scalars
    dists_kernel<<<(unsigned)(((size_t)Tt * Tt + 255) / 256), 256>>>(out);

    // 2. split x and qkv_w to bf16 hi/lo
    cvt_split<<<(BT * Cc + 255) / 256, 256>>>(x, p_ah, p_al, BT * Cc);
    cvt_split<<<(C3 * Cc + 255) / 256, 256>>>(qkv_w, p_wh, p_wl, C3 * Cc);

    // 3. QKV GEMM (double-buffered warp mma, occ 2)
    {
        dim3 grid(C3 / 128, BT / 128);
        mma_gemm_tn<<<grid, 256, GT_SMEM>>>(p_ah, p_al, p_wh, p_wl, p_qkv, Cc, Cc, Cc, C3);
    }

    // 4. split q/k into head-major bf16 hi/lo
    cvt_qk<<<(BT * Cc + 255) / 256, 256>>>();

    // 5. logits (warp mma, occ 2)
    {
        dim3 grid(Tt / 128, Tt / 128, BH);
        mma_logits<<<grid, 256>>>(dscales, out);
    }

    // 6. row softmax + energies (register-resident)
    {
        dim3 grid(Tt, BH);
        softmax_kernel<<<grid, 256>>>(out);
    }

    // 7. PV (warp mma, occ 2) -> g_o
    {
        dim3 grid(Tt / 128, BH);
        pv_mma<<<grid, 256>>>(out, p_o);
    }

    // 8. split o and proj_w, then proj GEMM -> out[0..N_OUT)
    cvt_split<<<(BT * Cc + 255) / 256, 256>>>(p_o, p_ah, p_al, BT * Cc);
    cvt_split<<<(Cc * Cc + 255) / 256, 256>>>(proj_w, p_wh, p_wl, Cc * Cc);
    {
        dim3 grid(Cc / 128, BT / 128);
        mma_gemm_tn<<<grid, 256, GT_SMEM>>>(p_ah, p_al, p_wh, p_wl, out, Cc, Cc, Cc, Cc);
    }
}

// round 9
// speedup vs baseline: 1.1623x; 1.0425x over previous
#include <cuda_runtime.h>
#include <cuda_bf16.h>
#include <math.h>
#include <stdint.h>

// ---------------- problem constants ----------------
#define Bb 2
#define Tt 2048
#define Cc 1024
#define Hh 16
#define DH 64
#define BT (Bb*Tt)            // 4096
#define C3 (3*Cc)             // 3072
#define BH (Bb*Hh)            // 32

// output buffer layout (flatten-concat of the reference tuple, fp32)
#define N_OUT   ((size_t)Bb*Tt*Cc)                 // 4,194,304
#define OFF_DE  (N_OUT)
#define OFF_FE  (N_OUT + 1)
#define OFF_ATTN (N_OUT + 2)                       // only 8-byte aligned!
#define N_ATTN  ((size_t)Bb*Hh*Tt*Tt)
#define OFF_DISTS (OFF_ATTN + N_ATTN)

// ---------------- scratch ----------------
__device__ float g_qkv[(size_t)BT * C3];                 // only V region used now
__device__ __nv_bfloat16 g_ah[(size_t)BT * Cc];          // activation hi (x, then o)
__device__ __nv_bfloat16 g_al[(size_t)BT * Cc];
__device__ __nv_bfloat16 g_wh[(size_t)C3 * Cc];
__device__ __nv_bfloat16 g_wl[(size_t)C3 * Cc];
__device__ __nv_bfloat16 g_qh[(size_t)BH * Tt * DH];     // head-major [bh][t][64]
__device__ __nv_bfloat16 g_ql[(size_t)BH * Tt * DH];
__device__ __nv_bfloat16 g_kh[(size_t)BH * Tt * DH];
__device__ __nv_bfloat16 g_kl[(size_t)BH * Tt * DH];

// ---------------- portable helpers (sm_80+) ----------------
__device__ __forceinline__ uint32_t smem_u32(const void* p) {
    uint32_t addr;
    asm("{ .reg .u64 tmp; cvta.to.shared.u64 tmp, %1; cvt.u32.u64 %0, tmp; }"
        : "=r"(addr) : "l"(p));
    return addr;
}
__device__ __forceinline__ void ldsm4(uint32_t r[4], uint32_t addr) {
    asm volatile("ldmatrix.sync.aligned.m8n8.x4.shared.b16 {%0,%1,%2,%3}, [%4];"
        : "=r"(r[0]), "=r"(r[1]), "=r"(r[2]), "=r"(r[3]) : "r"(addr));
}
__device__ __forceinline__ void mma_bf16(float c[4], const uint32_t a[4], const uint32_t b[2]) {
    asm volatile(
        "mma.sync.aligned.m16n8k16.row.col.f32.bf16.bf16.f32 "
        "{%0,%1,%2,%3}, {%4,%5,%6,%7}, {%8,%9}, {%0,%1,%2,%3};"
        : "+f"(c[0]), "+f"(c[1]), "+f"(c[2]), "+f"(c[3])
        : "r"(a[0]), "r"(a[1]), "r"(a[2]), "r"(a[3]), "r"(b[0]), "r"(b[1]));
}
__device__ __forceinline__ void cp_async16(uint32_t saddr, const void* gptr) {
    asm volatile("cp.async.cg.shared.global [%0], [%1], 16;" :: "r"(saddr), "l"(gptr));
}
#define CP_COMMIT() asm volatile("cp.async.commit_group;" ::: "memory")
#define CP_WAIT0()  asm volatile("cp.async.wait_group 0;" ::: "memory")

#define SPAD 40   // smem stride for 32-wide tiles
#define SK   72   // smem stride for 64-wide tiles

// ---------------- kernel: zero energy scalars + write dists (float2) ----------------
__global__ void dists_kernel(float* __restrict__ out) {
    size_t idx2 = (size_t)blockIdx.x * blockDim.x + threadIdx.x;
    if (idx2 < (size_t)Tt * Tt / 2) {
        int i  = (int)(idx2 / (Tt / 2));
        int j  = (int)(idx2 % (Tt / 2)) * 2;
        float2 v;
        v.x = fabsf((float)(i - j));
        v.y = fabsf((float)(i - j - 1));
        *(float2*)&out[OFF_DISTS + (size_t)i * Tt + j] = v;
    }
    if (idx2 == 0) { out[OFF_DE] = 0.f; out[OFF_FE] = 0.f; }
}

// ---------------- kernel: fp32 -> bf16 hi/lo split ----------------
__global__ void cvt_split(const float* __restrict__ src,
                          __nv_bfloat16* __restrict__ hi,
                          __nv_bfloat16* __restrict__ lo, int n) {
    int idx = blockIdx.x * blockDim.x + threadIdx.x;
    if (idx >= n) return;
    float v = src[idx];
    __nv_bfloat16 h = __float2bfloat16(v);
    hi[idx] = h;
    lo[idx] = __float2bfloat16(v - __bfloat162float(h));
}

// ---------------- warp-mma GEMM (cp.async double buffered, occ 2) ----------------
// mode 0: fp32 output to Cm (ldc). mode 1: QKV — q/k written split head-major, v fp32.
#define GT_TILE (128 * SPAD)
#define GT_SMEM (2 * 4 * GT_TILE * 2)        // 81920 bytes
__global__ __launch_bounds__(256, 2)
void mma_gemm_tn(const __nv_bfloat16* __restrict__ Ah, const __nv_bfloat16* __restrict__ Al,
                 const __nv_bfloat16* __restrict__ Wh, const __nv_bfloat16* __restrict__ Wl,
                 float* __restrict__ Cm, int K, int lda, int ldw, int ldc, int mode) {
    extern __shared__ __align__(16) __nv_bfloat16 dsmg[];
    int tid  = threadIdx.x;
    int warp = tid >> 5, lane = tid & 31;
    int m0 = blockIdx.y * 128;
    int n0 = blockIdx.x * 128;
    int wm = (warp & 3) * 32;
    int wn = (warp >> 2) * 64;

    const __nv_bfloat16* srcs[4] = { Ah + (size_t)m0 * lda, Al + (size_t)m0 * lda,
                                     Wh + (size_t)n0 * ldw, Wl + (size_t)n0 * ldw };
    int lds[4] = { lda, lda, ldw, ldw };
    uint32_t sb = smem_u32(dsmg);

    float c[16][4];
#pragma unroll
    for (int f = 0; f < 16; f++)
#pragma unroll
        for (int e = 0; e < 4; e++) c[f][e] = 0.f;

    int arow = lane & 15;
    int ablk = (lane >> 4) * 8;
    int nk = K / 32;

#pragma unroll
    for (int t = 0; t < 4; t++) {
        const __nv_bfloat16* s = srcs[t];
        int ld = lds[t];
#pragma unroll
        for (int it = 0; it < 2; it++) {
            int idx = tid + it * 256;
            int row = idx >> 2;
            int cc  = idx & 3;
            cp_async16(sb + (t * GT_TILE + row * SPAD + cc * 8) * 2,
                       s + (size_t)row * ld + cc * 8);
        }
    }
    CP_COMMIT();

    for (int kc = 0; kc < nk; kc++) {
        CP_WAIT0();
        __syncthreads();
        if (kc + 1 < nk) {
            int nb = (kc + 1) & 1;
            int k0 = (kc + 1) * 32;
#pragma unroll
            for (int t = 0; t < 4; t++) {
                const __nv_bfloat16* s = srcs[t] + k0;
                int ld = lds[t];
#pragma unroll
                for (int it = 0; it < 2; it++) {
                    int idx = tid + it * 256;
                    int row = idx >> 2;
                    int cc  = idx & 3;
                    cp_async16(sb + ((nb * 4 + t) * GT_TILE + row * SPAD + cc * 8) * 2,
                               s + (size_t)row * ld + cc * 8);
                }
            }
            CP_COMMIT();
        }
        uint32_t bo = (uint32_t)((kc & 1) * 4 * GT_TILE) * 2;

#pragma unroll
        for (int ks = 0; ks < 32; ks += 16) {
            uint32_t a_hi[2][4], a_lo[2][4];
#pragma unroll
            for (int mf = 0; mf < 2; mf++) {
                uint32_t off = ((wm + mf * 16 + arow) * SPAD + ks + ablk) * 2;
                ldsm4(a_hi[mf], sb + bo + 0 * GT_TILE * 2 + off);
                ldsm4(a_lo[mf], sb + bo + 1 * GT_TILE * 2 + off);
            }
            uint32_t b_hi[8][2], b_lo[8][2];
#pragma unroll
            for (int pr = 0; pr < 4; pr++) {
                uint32_t off = ((wn + pr * 16 + arow) * SPAD + ks + ablk) * 2;
                uint32_t t4[4];
                ldsm4(t4, sb + bo + 2 * GT_TILE * 2 + off);
                b_hi[pr*2+0][0] = t4[0]; b_hi[pr*2+0][1] = t4[2];
                b_hi[pr*2+1][0] = t4[1]; b_hi[pr*2+1][1] = t4[3];
                ldsm4(t4, sb + bo + 3 * GT_TILE * 2 + off);
                b_lo[pr*2+0][0] = t4[0]; b_lo[pr*2+0][1] = t4[2];
                b_lo[pr*2+1][0] = t4[1]; b_lo[pr*2+1][1] = t4[3];
            }
#pragma unroll
            for (int mf = 0; mf < 2; mf++)
#pragma unroll
                for (int nf = 0; nf < 8; nf++) {
                    mma_bf16(c[mf*8+nf], a_hi[mf], b_hi[nf]);
                    mma_bf16(c[mf*8+nf], a_hi[mf], b_lo[nf]);
                    mma_bf16(c[mf*8+nf], a_lo[mf], b_hi[nf]);
                }
        }
    }

    int r = lane >> 2, q2 = (lane & 3) * 2;
    if (mode == 0 || n0 >= 2048) {
        // plain fp32 output (full matrix, or the V third of QKV)
#pragma unroll
        for (int mf = 0; mf < 2; mf++)
#pragma unroll
            for (int nf = 0; nf < 8; nf++) {
                int m = m0 + wm + mf * 16 + r;
                int n = n0 + wn + nf * 8 + q2;
                float* f = c[mf*8+nf];
                *(float2*)&Cm[(size_t)m * ldc + n]       = make_float2(f[0], f[1]);
                *(float2*)&Cm[(size_t)(m + 8) * ldc + n] = make_float2(f[2], f[3]);
            }
    } else {
        // q or k: write bf16 hi/lo, head-major [bh][t][64]
        __nv_bfloat16* Hd = (n0 < 1024) ? g_qh : g_kh;
        __nv_bfloat16* Ld = (n0 < 1024) ? g_ql : g_kl;
#pragma unroll
        for (int mf = 0; mf < 2; mf++)
#pragma unroll
            for (int nf = 0; nf < 8; nf++) {
                int m = m0 + wm + mf * 16 + r;
                int n = n0 + wn + nf * 8 + q2;
                int nin = n & 1023;
                int h = nin >> 6, d = nin & 63;
                float* f = c[mf*8+nf];
#pragma unroll
                for (int rr = 0; rr < 2; rr++) {
                    int mm = m + rr * 8;
                    int b = mm >> 11, t = mm & 2047;
                    size_t dst = (((size_t)(b * Hh + h) * Tt) + t) * DH + d;
                    float v0 = f[rr*2+0], v1 = f[rr*2+1];
                    __nv_bfloat16 h0 = __float2bfloat16(v0);
                    __nv_bfloat16 h1 = __float2bfloat16(v1);
                    __nv_bfloat162 hv; hv.x = h0; hv.y = h1;
                    __nv_bfloat162 lv;
                    lv.x = __float2bfloat16(v0 - __bfloat162float(h0));
                    lv.y = __float2bfloat16(v1 - __bfloat162float(h1));
                    *(__nv_bfloat162*)&Hd[dst] = hv;
                    *(__nv_bfloat162*)&Ld[dst] = lv;
                }
            }
    }
}

// ---------------- warp-mma logits (single load phase, occ 2) ----------------
#define LT_TILE (128 * SK)                  // elems per 64-wide tile
#define LT_SMEM (4 * LT_TILE * 2)           // 73728 bytes
__global__ __launch_bounds__(256, 2)
void mma_logits(const float* __restrict__ dscales, float* __restrict__ out) {
    if (blockIdx.x > blockIdx.y) return;
    extern __shared__ __align__(16) __nv_bfloat16 dsml[];
    int tid  = threadIdx.x;
    int warp = tid >> 5, lane = tid & 31;
    int bh = blockIdx.z;
    int h = bh & 15;
    int i0 = blockIdx.y * 128;
    int j0 = blockIdx.x * 128;
    int wm = (warp & 3) * 32;
    int wn = (warp >> 2) * 64;

    size_t qbase = ((size_t)bh * Tt + i0) * DH;
    size_t kbase = ((size_t)bh * Tt + j0) * DH;
    const __nv_bfloat16* srcs[4] = { g_qh + qbase, g_ql + qbase, g_kh + kbase, g_kl + kbase };
    uint32_t sb = smem_u32(dsml);

    // load 4 tiles of 128x64 via cp.async (1024 uint4 each, 4 per thread)
#pragma unroll
    for (int t = 0; t < 4; t++) {
        const __nv_bfloat16* s = srcs[t];
#pragma unroll
        for (int it = 0; it < 4; it++) {
            int idx = tid + it * 256;
            int row = idx >> 3;
            int cc  = idx & 7;
            cp_async16(sb + (t * LT_TILE + row * SK + cc * 8) * 2,
                       s + (size_t)row * DH + cc * 8);
        }
    }
    CP_COMMIT();

    float c[16][4];
#pragma unroll
    for (int f = 0; f < 16; f++)
#pragma unroll
        for (int e = 0; e < 4; e++) c[f][e] = 0.f;

    int arow = lane & 15;
    int ablk = (lane >> 4) * 8;

    CP_WAIT0();
    __syncthreads();

#pragma unroll
    for (int ks = 0; ks < 64; ks += 16) {
        uint32_t a_hi[2][4], a_lo[2][4];
#pragma unroll
        for (int mf = 0; mf < 2; mf++) {
            uint32_t off = ((wm + mf * 16 + arow) * SK + ks + ablk) * 2;
            ldsm4(a_hi[mf], sb + 0 * LT_TILE * 2 + off);
            ldsm4(a_lo[mf], sb + 1 * LT_TILE * 2 + off);
        }
        uint32_t b_hi[8][2], b_lo[8][2];
#pragma unroll
        for (int pr = 0; pr < 4; pr++) {
            uint32_t off = ((wn + pr * 16 + arow) * SK + ks + ablk) * 2;
            uint32_t t4[4];
            ldsm4(t4, sb + 2 * LT_TILE * 2 + off);
            b_hi[pr*2+0][0] = t4[0]; b_hi[pr*2+0][1] = t4[2];
            b_hi[pr*2+1][0] = t4[1]; b_hi[pr*2+1][1] = t4[3];
            ldsm4(t4, sb + 3 * LT_TILE * 2 + off);
            b_lo[pr*2+0][0] = t4[0]; b_lo[pr*2+0][1] = t4[2];
            b_lo[pr*2+1][0] = t4[1]; b_lo[pr*2+1][1] = t4[3];
        }
#pragma unroll
        for (int mf = 0; mf < 2; mf++)
#pragma unroll
            for (int nf = 0; nf < 8; nf++) {
                mma_bf16(c[mf*8+nf], a_hi[mf], b_hi[nf]);
                mma_bf16(c[mf*8+nf], a_hi[mf], b_lo[nf]);
                mma_bf16(c[mf*8+nf], a_lo[mf], b_hi[nf]);
            }
    }

    float ds = dscales[h];
    int r = lane >> 2, q2 = (lane & 3) * 2;
    size_t abase = OFF_ATTN + (size_t)bh * Tt * Tt;
#pragma unroll
    for (int mf = 0; mf < 2; mf++)
#pragma unroll
        for (int nf = 0; nf < 8; nf++) {
            int i = i0 + wm + mf * 16 + r;
            int j = j0 + wn + nf * 8 + q2;
            float* f = c[mf*8+nf];
            float2 v0, v1;
            v0.x = f[0] * 0.125f - ds * (float)(i - j);
            v0.y = f[1] * 0.125f - ds * (float)(i - j - 1);
            v1.x = f[2] * 0.125f - ds * (float)(i + 8 - j);
            v1.y = f[3] * 0.125f - ds * (float)(i + 8 - j - 1);
            *(float2*)&out[abase + (size_t)i * Tt + j]       = v0;
            *(float2*)&out[abase + (size_t)(i + 8) * Tt + j] = v1;
        }
}

// ---------------- softmax + energies: register-resident ----------------
__global__ __launch_bounds__(256) void softmax_kernel(float* __restrict__ d_out) {
    __shared__ float red[4][8];
    int i   = blockIdx.x;
    int bh  = blockIdx.y;
    int tid = threadIdx.x;
    int lane = tid & 31, wid = tid >> 5;
    size_t arow = OFF_ATTN + ((size_t)bh * Tt + i) * Tt;

    float v[8];
    float lmax = -INFINITY;
#pragma unroll
    for (int k = 0; k < 4; k++) {
        int j = 2 * (tid + 256 * k);
        float a = -INFINITY, b = -INFINITY;
        if (j <= i) {
            float2 s = *(const float2*)&d_out[arow + j];
            a = s.x;
            if (j + 1 <= i) b = s.y;
        }
        v[2*k] = a; v[2*k+1] = b;
        lmax = fmaxf(lmax, fmaxf(a, b));
    }
#pragma unroll
    for (int off = 16; off > 0; off >>= 1)
        lmax = fmaxf(lmax, __shfl_xor_sync(0xFFFFFFFFu, lmax, off));
    if (lane == 0) red[0][wid] = lmax;
    __syncthreads();
    float m = red[0][0];
#pragma unroll
    for (int w = 1; w < 8; w++) m = fmaxf(m, red[0][w]);

    float lsum = 0.f;
#pragma unroll
    for (int k = 0; k < 8; k++) {
        v[k] = __expf(v[k] - m);
        lsum += v[k];
    }
#pragma unroll
    for (int off = 16; off > 0; off >>= 1)
        lsum += __shfl_xor_sync(0xFFFFFFFFu, lsum, off);
    if (lane == 0) red[1][wid] = lsum;
    __syncthreads();
    float tot = 0.f;
#pragma unroll
    for (int w = 0; w < 8; w++) tot += red[1][w];
    float inv = 1.f / tot;

    float de = 0.f, fe = 0.f;
#pragma unroll
    for (int k = 0; k < 4; k++) {
        int j = 2 * (tid + 256 * k);
        float a0 = v[2*k] * inv;
        float a1 = v[2*k+1] * inv;
        *(float2*)&d_out[arow + j] = make_float2(a0, a1);
        de += a0 * (float)(i - j) + a1 * (float)(i - j - 1);
        fe -= a0 * __logf(a0 + 1e-9f) + a1 * __logf(a1 + 1e-9f);
    }
#pragma unroll
    for (int off = 16; off > 0; off >>= 1) {
        de += __shfl_xor_sync(0xFFFFFFFFu, de, off);
        fe += __shfl_xor_sync(0xFFFFFFFFu, fe, off);
    }
    if (lane == 0) { red[2][wid] = de; red[3][wid] = fe; }
    __syncthreads();
    if (tid == 0) {
        float sde = 0.f, sfe = 0.f;
#pragma unroll
        for (int w = 0; w < 8; w++) { sde += red[2][w]; sfe += red[3][w]; }
        atomicAdd(&d_out[OFF_DE], sde * (1.f / 65536.f));
        atomicAdd(&d_out[OFF_FE], sfe * (1.f / 65536.f));
    }
}

// ---------------- PV via warp-mma (occ 2): writes o split bf16 hi/lo ----------------
__global__ __launch_bounds__(256, 2) void pv_mma(const float* __restrict__ d_out_c) {
    __shared__ __align__(16) __nv_bfloat16 sAh[128 * SPAD];
    __shared__ __align__(16) __nv_bfloat16 sAl[128 * SPAD];
    __shared__ __align__(16) __nv_bfloat16 sVh[64 * SPAD];
    __shared__ __align__(16) __nv_bfloat16 sVl[64 * SPAD];
    int it = blockIdx.x;
    int bh = blockIdx.y;
    int b = bh >> 4, h = bh & 15;
    int i0 = it * 128;
    int tid  = threadIdx.x;
    int warp = tid >> 5, lane = tid & 31;
    int wm = (warp & 3) * 32;
    int wn = (warp >> 2) * 32;

    const float* Arow = d_out_c + OFF_ATTN + (size_t)bh * Tt * Tt;
    const float* Vb = g_qkv + (size_t)(b * Tt) * C3 + 2 * Cc + h * DH;

    uint32_t sbAh = smem_u32(sAh), sbAl = smem_u32(sAl);
    uint32_t sbVh = smem_u32(sVh), sbVl = smem_u32(sVl);

    float c[8][4];
#pragma unroll
    for (int f = 0; f < 8; f++)
#pragma unroll
        for (int e = 0; e < 4; e++) c[f][e] = 0.f;

    int arw = lane & 15;
    int ablk = (lane >> 4) * 8;
    int kmax = i0 + 128;

    for (int k0 = 0; k0 < kmax; k0 += 32) {
#pragma unroll
        for (int t = 0; t < 8; t++) {
            int idx = tid + t * 256;
            int row = idx >> 4;
            int cc  = idx & 15;
            float2 s = *(const float2*)&Arow[(size_t)(i0 + row) * Tt + k0 + cc * 2];
            __nv_bfloat16 h0 = __float2bfloat16(s.x);
            __nv_bfloat16 h1 = __float2bfloat16(s.y);
            sAh[row * SPAD + cc*2]     = h0;
            sAh[row * SPAD + cc*2 + 1] = h1;
            sAl[row * SPAD + cc*2]     = __float2bfloat16(s.x - __bfloat162float(h0));
            sAl[row * SPAD + cc*2 + 1] = __float2bfloat16(s.y - __bfloat162float(h1));
        }
#pragma unroll
        for (int t = 0; t < 8; t++) {
            int idx = tid + t * 256;
            int kk = idx >> 6;
            int d  = idx & 63;
            float xv = Vb[(size_t)(k0 + kk) * C3 + d];
            __nv_bfloat16 hh = __float2bfloat16(xv);
            sVh[d * SPAD + kk] = hh;
            sVl[d * SPAD + kk] = __float2bfloat16(xv - __bfloat162float(hh));
        }
        __syncthreads();

#pragma unroll
        for (int ks = 0; ks < 32; ks += 16) {
            uint32_t a_hi[2][4], a_lo[2][4];
#pragma unroll
            for (int mf = 0; mf < 2; mf++) {
                uint32_t off = ((wm + mf * 16 + arw) * SPAD + ks + ablk) * 2;
                ldsm4(a_hi[mf], sbAh + off);
                ldsm4(a_lo[mf], sbAl + off);
            }
            uint32_t b_hi[4][2], b_lo[4][2];
#pragma unroll
            for (int pr = 0; pr < 2; pr++) {
                uint32_t off = ((wn + pr * 16 + arw) * SPAD + ks + ablk) * 2;
                uint32_t t4[4];
                ldsm4(t4, sbVh + off);
                b_hi[pr*2+0][0] = t4[0]; b_hi[pr*2+0][1] = t4[2];
                b_hi[pr*2+1][0] = t4[1]; b_hi[pr*2+1][1] = t4[3];
                ldsm4(t4, sbVl + off);
                b_lo[pr*2+0][0] = t4[0]; b_lo[pr*2+0][1] = t4[2];
                b_lo[pr*2+1][0] = t4[1]; b_lo[pr*2+1][1] = t4[3];
            }
#pragma unroll
            for (int mf = 0; mf < 2; mf++)
#pragma unroll
                for (int nf = 0; nf < 4; nf++) {
                    mma_bf16(c[mf*4+nf], a_hi[mf], b_hi[nf]);
                    mma_bf16(c[mf*4+nf], a_hi[mf], b_lo[nf]);
                    mma_bf16(c[mf*4+nf], a_lo[mf], b_hi[nf]);
                }
        }
        __syncthreads();
    }

    // epilogue: split to bf16 hi/lo, write activation layout [bt][c]
    int r = lane >> 2, q2 = (lane & 3) * 2;
#pragma unroll
    for (int mf = 0; mf < 2; mf++)
#pragma unroll
        for (int nf = 0; nf < 4; nf++) {
            int n = wn + nf * 8 + q2;
            float* f = c[mf*4+nf];
#pragma unroll
            for (int rr = 0; rr < 2; rr++) {
                int m = i0 + wm + mf * 16 + r + rr * 8;
                size_t dst = (size_t)(b * Tt + m) * Cc + h * DH + n;
                float v0 = f[rr*2+0], v1 = f[rr*2+1];
                __nv_bfloat16 h0 = __float2bfloat16(v0);
                __nv_bfloat16 h1 = __float2bfloat16(v1);
                __nv_bfloat162 hv; hv.x = h0; hv.y = h1;
                __nv_bfloat162 lv;
                lv.x = __float2bfloat16(v0 - __bfloat162float(h0));
                lv.y = __float2bfloat16(v1 - __bfloat162float(h1));
                *(__nv_bfloat162*)&g_ah[dst] = hv;
                *(__nv_bfloat162*)&g_al[dst] = lv;
            }
        }
}

// ---------------- launch ----------------
extern "C" void kernel_launch(void* const* d_in, const int* in_sizes, int n_in,
                              void* d_out, int out_size) {
    const float* x       = (const float*)d_in[0];
    const float* qkv_w   = (const float*)d_in[1];
    const float* proj_w  = (const float*)d_in[2];
    const float* dscales = (const float*)d_in[3];
    float* out = (float*)d_out;

    float *p_qkv;
    __nv_bfloat16 *p_ah, *p_al, *p_wh, *p_wl;
    cudaGetSymbolAddress((void**)&p_qkv, g_qkv);
    cudaGetSymbolAddress((void**)&p_ah,  g_ah);
    cudaGetSymbolAddress((void**)&p_al,  g_al);
    cudaGetSymbolAddress((void**)&p_wh,  g_wh);
    cudaGetSymbolAddress((void**)&p_wl,  g_wl);

    cudaFuncSetAttribute(mma_gemm_tn, cudaFuncAttributeMaxDynamicSharedMemorySize, GT_SMEM);
    cudaFuncSetAttribute(mma_logits,  cudaFuncAttributeMaxDynamicSharedMemorySize, LT_SMEM);

    // 1. dists + zero scalars (float2)
    dists_kernel<<<(unsigned)(((size_t)Tt * Tt / 2 + 255) / 256), 256>>>(out);

    // 2. split x and qkv_w to bf16 hi/lo
    cvt_split<<<(BT * Cc + 255) / 256, 256>>>(x, p_ah, p_al, BT * Cc);
    cvt_split<<<(C3 * Cc + 255) / 256, 256>>>(qkv_w, p_wh, p_wl, C3 * Cc);

    // 3. QKV GEMM (mode 1: q/k split head-major, v fp32)
    {
        dim3 grid(C3 / 128, BT / 128);
        mma_gemm_tn<<<grid, 256, GT_SMEM>>>(p_ah, p_al, p_wh, p_wl, p_qkv, Cc, Cc, Cc, C3, 1);
    }

    // 4. logits (single-phase warp mma, occ 2)
    {
        dim3 grid(Tt / 128, Tt / 128, BH);
        mma_logits<<<grid, 256, LT_SMEM>>>(dscales, out);
    }

    // 5. row softmax + energies
    {
        dim3 grid(Tt, BH);
        softmax_kernel<<<grid, 256>>>(out);
    }

    // 6. PV -> o split bf16 directly into g_ah/g_al
    {
        dim3 grid(Tt / 128, BH);
        pv_mma<<<grid, 256>>>(out);
    }

    // 7. split proj_w, then proj GEMM (mode 0) -> out[0..N_OUT)
    cvt_split<<<(Cc * Cc + 255) / 256, 256>>>(proj_w, p_wh, p_wl, Cc * Cc);
    {
        dim3 grid(Cc / 128, BT / 128);
        mma_gemm_tn<<<grid, 256, GT_SMEM>>>(p_ah, p_al, p_wh, p_wl, out, Cc, Cc, Cc, Cc, 0);
    }
}